// round 9
// baseline (speedup 1.0000x reference)
#include <cuda_runtime.h>
#include <cuda_bf16.h>

#define BHALF 4096
#define NROW  8192
#define DIM   256
#define INV_T (1.0f/0.07f)
#define LOG2E 1.4426950408889634f

#define TILE_M 128
#define SM_STRIDE 264            // 256 + 8 bf16 pad -> conflict-free fragment loads
#define TILE_BYTES (TILE_M * SM_STRIDE * 2)          // 67584
#define SMEM_BYTES (3 * TILE_BYTES)                  // A + 2x B = 202752

#define NTILE 64                 // 8192 / 128
#define NPAIR 2080               // upper-triangle tile count
#define NTHREADS 512             // 16 warps, 4x4 warp grid, 32x32 per warp

__device__ __nv_bfloat16 g_zn[NROW * DIM];   // normalized rows, bf16 (4 MB)
__device__ float g_sumexp[NROW];
__device__ float g_pos[NROW];
__device__ volatile unsigned g_gen;          // grid-barrier generation
__device__ unsigned g_count;                 // grid-barrier arrivals
__device__ unsigned g_done;                  // tail election

// ---------------------------------------------------------------------------
// soft grid barrier (single-wave persistent grid only)
// ---------------------------------------------------------------------------
__device__ __forceinline__ void grid_barrier(unsigned nblk) {
    __threadfence();
    __syncthreads();
    if (threadIdx.x == 0) {
        unsigned gen = g_gen;
        if (atomicAdd(&g_count, 1) == nblk - 1) {
            g_count = 0;
            __threadfence();
            g_gen = gen + 1;
        } else {
            while (g_gen == gen) {}
            __threadfence();
        }
    }
    __syncthreads();
}

// ---------------------------------------------------------------------------
// fast exp via 2^y on the FMA pipe
// ---------------------------------------------------------------------------
__device__ __forceinline__ float fast_exp2(float y) {
    float t  = y + 12582912.0f;          // round-to-nearest-int trick (1.5*2^23)
    int   i  = __float_as_int(t);
    float nf = t - 12582912.0f;
    float f  = y - nf;                   // f in [-0.5, 0.5]
    float p  = fmaf(1.3333558e-3f, f, 9.6181291e-3f);
    p = fmaf(p, f, 5.5504109e-2f);
    p = fmaf(p, f, 2.4022651e-1f);
    p = fmaf(p, f, 6.9314718e-1f);
    p = fmaf(p, f, 1.0f);
    return p * __int_as_float((i << 23) + 0x3F800000);
}

__device__ __forceinline__ void mma16816(float c[4],
                                         unsigned a0, unsigned a1, unsigned a2, unsigned a3,
                                         unsigned b0, unsigned b1) {
    asm volatile(
        "mma.sync.aligned.m16n8k16.row.col.f32.bf16.bf16.f32 "
        "{%0,%1,%2,%3}, {%4,%5,%6,%7}, {%8,%9}, {%0,%1,%2,%3};\n"
        : "+f"(c[0]), "+f"(c[1]), "+f"(c[2]), "+f"(c[3])
        : "r"(a0), "r"(a1), "r"(a2), "r"(a3), "r"(b0), "r"(b1));
}

__device__ __forceinline__ void cp_async16(void* smem_dst, const void* gsrc) {
    unsigned s = (unsigned)__cvta_generic_to_shared(smem_dst);
    asm volatile("cp.async.cg.shared.global [%0], [%1], 16;\n" :: "r"(s), "l"(gsrc));
}
__device__ __forceinline__ void cp_commit() {
    asm volatile("cp.async.commit_group;\n" ::: "memory");
}
__device__ __forceinline__ void cp_wait1() {
    asm volatile("cp.async.wait_group 1;\n" ::: "memory");
}
__device__ __forceinline__ void cp_wait0() {
    asm volatile("cp.async.wait_group 0;\n" ::: "memory");
}

__device__ __forceinline__ void load_tile_cp(__nv_bfloat16* dst,
                                             const __nv_bfloat16* src, int tid) {
    #pragma unroll
    for (int it = 0; it < 8; it++) {
        int idx = tid + it * NTHREADS;     // 4096 16B chunks
        int r = idx >> 5, c8 = idx & 31;
        cp_async16(dst + r * SM_STRIDE + c8 * 8, src + r * 256 + c8 * 8);
    }
}

__device__ __forceinline__ void load_tile_sync(__nv_bfloat16* dst,
                                               const __nv_bfloat16* src, int tid) {
    const uint4* gsrc = (const uint4*)src;
    #pragma unroll
    for (int it = 0; it < 8; it++) {
        int idx = tid + it * NTHREADS;
        int r = idx >> 5, c8 = idx & 31;
        *(uint4*)(dst + r * SM_STRIDE + c8 * 8) = gsrc[r * 32 + c8];
    }
}

// decode linear upper-triangle tile index q -> (i, j)
__device__ __forceinline__ void decode_tile(int q, int& i, int& j) {
    i = 0;
    int rem = q;
    while (rem >= NTILE - i) { rem -= NTILE - i; i++; }
    j = i + rem;
}

// rows owned by this thread: iT*128 + wm*32 + mt*16 + g + h*8
__device__ __forceinline__ void flush_rsum(float (&rsum)[2][2], int iT,
                                           int wm, int g, int tig) {
    #pragma unroll
    for (int mt = 0; mt < 2; mt++)
        #pragma unroll
        for (int h = 0; h < 2; h++) {
            float v = rsum[mt][h];
            v += __shfl_xor_sync(0xffffffffu, v, 1);
            v += __shfl_xor_sync(0xffffffffu, v, 2);
            if (tig == 0)
                atomicAdd(&g_sumexp[iT * TILE_M + wm * 32 + mt * 16 + g + h * 8], v);
            rsum[mt][h] = 0.0f;
        }
}

__device__ __forceinline__ void flush_csum(float (&csum)[4][2], int jP,
                                           int wn, int g, int tig) {
    #pragma unroll
    for (int nt = 0; nt < 4; nt++)
        #pragma unroll
        for (int p = 0; p < 2; p++) {
            float v = csum[nt][p];
            v += __shfl_xor_sync(0xffffffffu, v, 4);
            v += __shfl_xor_sync(0xffffffffu, v, 8);
            v += __shfl_xor_sync(0xffffffffu, v, 16);
            if (g == 0)
                atomicAdd(&g_sumexp[jP * TILE_M + wn * 32 + nt * 8 + tig * 2 + p], v);
        }
}

// ---------------------------------------------------------------------------
// one-warp row normalize
// ---------------------------------------------------------------------------
__device__ __forceinline__ void norm_row(int row, const float* __restrict__ z_i,
                                         const float* __restrict__ z_j, int lane) {
    const float* src = (row < BHALF) ? (z_i + (size_t)row * DIM)
                                     : (z_j + (size_t)(row - BHALF) * DIM);
    float4 v0 = ((const float4*)src)[lane * 2];
    float4 v1 = ((const float4*)src)[lane * 2 + 1];
    float ss = v0.x*v0.x + v0.y*v0.y + v0.z*v0.z + v0.w*v0.w
             + v1.x*v1.x + v1.y*v1.y + v1.z*v1.z + v1.w*v1.w;
    #pragma unroll
    for (int o = 16; o; o >>= 1) ss += __shfl_xor_sync(0xffffffffu, ss, o);
    float inv = 1.0f / fmaxf(sqrtf(ss), 1e-8f);

    __nv_bfloat162 h0 = __floats2bfloat162_rn(v0.x*inv, v0.y*inv);
    __nv_bfloat162 h1 = __floats2bfloat162_rn(v0.z*inv, v0.w*inv);
    __nv_bfloat162 h2 = __floats2bfloat162_rn(v1.x*inv, v1.y*inv);
    __nv_bfloat162 h3 = __floats2bfloat162_rn(v1.z*inv, v1.w*inv);
    uint4 u;
    u.x = *(unsigned*)&h0; u.y = *(unsigned*)&h1;
    u.z = *(unsigned*)&h2; u.w = *(unsigned*)&h3;
    *(uint4*)(g_zn + (size_t)row * DIM + lane * 8) = u;
    if (lane == 0) { g_sumexp[row] = 0.0f; g_pos[row] = 0.0f; }
}

// ---------------------------------------------------------------------------
// fused persistent kernel: normalize -> grid barrier -> symmetric GEMM with
// fused softmax-sum epilogue -> last-block loss tail.
// 512 threads, 4x4 warp grid, 32x32 warp tile (low reg pressure, 4 w/SMSP).
// ---------------------------------------------------------------------------
__global__ void __launch_bounds__(NTHREADS) ntxent_fused_kernel(
    const float* __restrict__ z_i, const float* __restrict__ z_j,
    float* __restrict__ out)
{
    extern __shared__ __nv_bfloat16 smem[];
    __nv_bfloat16* As  = smem;
    __nv_bfloat16* Bs0 = smem + TILE_M * SM_STRIDE;
    __nv_bfloat16* Bs1 = Bs0 + TILE_M * SM_STRIDE;

    const int tid  = threadIdx.x;
    const int warp = tid >> 5, lane = tid & 31;
    const int g    = lane >> 2, tig = lane & 3;
    const int wm   = warp >> 2, wn = warp & 3;   // 4x4 grid -> 32x32 per warp
    const unsigned nblk = gridDim.x;

    // ---- phase 1: normalize ----
    {
        int stride = nblk * 16;
        for (int r0 = blockIdx.x * 16 + warp; r0 < NROW; r0 += 2 * stride) {
            int r1 = r0 + stride;
            norm_row(r0, z_i, z_j, lane);
            if (r1 < NROW) norm_row(r1, z_i, z_j, lane);
        }
    }

    grid_barrier(nblk);

    // ---- phase 2: GEMM over balanced contiguous triangle ranges ----
    int bid = blockIdx.x;
    int q0  = (int)(((long long)bid * NPAIR) / nblk);
    int q1  = (int)(((long long)(bid + 1) * NPAIR) / nblk);

    if (q0 < q1) {
        int iCur, jCur;
        decode_tile(q0, iCur, jCur);

        load_tile_sync(As, g_zn + (size_t)iCur * TILE_M * DIM, tid);
        int iLoaded = iCur;
        load_tile_cp(Bs0, g_zn + (size_t)jCur * TILE_M * DIM, tid);
        cp_commit();

        float rsum[2][2];
        rsum[0][0] = rsum[0][1] = rsum[1][0] = rsum[1][1] = 0.f;

        for (int q = q0; q < q1; q++) {
            int buf = (q - q0) & 1;
            int iN = iCur, jN = jCur + 1;
            if (jN == NTILE) { iN++; jN = iN; }

            __syncthreads();                    // prior tile fully consumed

            if (q + 1 < q1)
                load_tile_cp(buf ? Bs0 : Bs1, g_zn + (size_t)jN * TILE_M * DIM, tid);
            cp_commit();                        // uniform group count

            if (iCur != iLoaded) {
                flush_rsum(rsum, iLoaded, wm, g, tig);
                load_tile_sync(As, g_zn + (size_t)iCur * TILE_M * DIM, tid);
                iLoaded = iCur;
            }

            cp_wait1();
            __syncthreads();

            const __nv_bfloat16* Bb = buf ? Bs1 : Bs0;

            float acc[2][4][4];
            #pragma unroll
            for (int mt = 0; mt < 2; mt++)
                #pragma unroll
                for (int nt = 0; nt < 4; nt++)
                    #pragma unroll
                    for (int ci = 0; ci < 4; ci++) acc[mt][nt][ci] = 0.f;

            #pragma unroll
            for (int kk = 0; kk < 16; kk++) {
                const int k0 = kk * 16 + tig * 2;
                unsigned a[2][4], b[4][2];
                #pragma unroll
                for (int mt = 0; mt < 2; mt++) {
                    const __nv_bfloat16* ap =
                        As + (wm * 32 + mt * 16 + g) * SM_STRIDE + k0;
                    a[mt][0] = *(const unsigned*)(ap);
                    a[mt][1] = *(const unsigned*)(ap + 8 * SM_STRIDE);
                    a[mt][2] = *(const unsigned*)(ap + 8);
                    a[mt][3] = *(const unsigned*)(ap + 8 * SM_STRIDE + 8);
                }
                #pragma unroll
                for (int nt = 0; nt < 4; nt++) {
                    const __nv_bfloat16* bp =
                        Bb + (wn * 32 + nt * 8 + g) * SM_STRIDE + k0;
                    b[nt][0] = *(const unsigned*)(bp);
                    b[nt][1] = *(const unsigned*)(bp + 8);
                }
                #pragma unroll
                for (int mt = 0; mt < 2; mt++)
                    #pragma unroll
                    for (int nt = 0; nt < 4; nt++)
                        mma16816(acc[mt][nt], a[mt][0], a[mt][1], a[mt][2], a[mt][3],
                                 b[nt][0], b[nt][1]);
            }

            // ---- fused epilogue ----
            const bool diag = (jCur == iCur);
            const bool pos  = (jCur == iCur + 32);
            float csum[4][2];
            #pragma unroll
            for (int nt = 0; nt < 4; nt++) { csum[nt][0] = 0.f; csum[nt][1] = 0.f; }

            #pragma unroll
            for (int mt = 0; mt < 2; mt++)
                #pragma unroll
                for (int nt = 0; nt < 4; nt++)
                    #pragma unroll
                    for (int ci = 0; ci < 4; ci++) {
                        float v = acc[mt][nt][ci];
                        float e = fast_exp2(v * (INV_T * LOG2E));
                        if (diag | pos) {
                            int row = iCur * TILE_M + wm * 32 + mt * 16 + g + (ci >> 1) * 8;
                            int col = jCur * TILE_M + wn * 32 + nt * 8 + tig * 2 + (ci & 1);
                            if (pos & (col == row + BHALF)) {
                                float pv = v * INV_T;
                                g_pos[row] = pv;
                                g_pos[col] = pv;
                            }
                            if (diag & (col == row)) e = 0.0f;
                        }
                        rsum[mt][ci >> 1] += e;
                        csum[nt][ci & 1]  += e;
                    }

            if (!diag) flush_csum(csum, jCur, wn, g, tig);

            iCur = iN; jCur = jN;
        }

        flush_rsum(rsum, iLoaded, wm, g, tig);
        cp_wait0();
    }

    // ---- phase 3: last block computes the loss ----
    __threadfence();
    __syncthreads();
    __shared__ unsigned amLast;
    if (tid == 0)
        amLast = (atomicAdd(&g_done, 1) == nblk - 1) ? 1u : 0u;
    __syncthreads();

    if (amLast) {
        __threadfence();
        float s = 0.0f;
        for (int k = tid; k < NROW; k += NTHREADS)
            s += logf(__ldcg(&g_sumexp[k])) - __ldcg(&g_pos[k]);
        #pragma unroll
        for (int o = 16; o; o >>= 1) s += __shfl_xor_sync(0xffffffffu, s, o);
        __shared__ float sw[16];
        if (lane == 0) sw[warp] = s;
        __syncthreads();
        if (tid == 0) {
            float v = 0.0f;
            #pragma unroll
            for (int w = 0; w < 16; w++) v += sw[w];
            out[0] = v / (float)NROW;
            g_done = 0;              // reset for next graph replay
        }
    }
}

extern "C" void kernel_launch(void* const* d_in, const int* in_sizes, int n_in,
                              void* d_out, int out_size) {
    const float* z_i = (const float*)d_in[0];
    const float* z_j = (const float*)d_in[1];
    float* out = (float*)d_out;

    int dev = 0, nsm = 148;
    cudaGetDevice(&dev);
    cudaDeviceGetAttribute(&nsm, cudaDevAttrMultiProcessorCount, dev);
    if (nsm < 1) nsm = 148;
    if (nsm > 512) nsm = 512;

    cudaFuncSetAttribute(ntxent_fused_kernel,
                         cudaFuncAttributeMaxDynamicSharedMemorySize, SMEM_BYTES);

    ntxent_fused_kernel<<<nsm, NTHREADS, SMEM_BYTES>>>(z_i, z_j, out);
}

// round 10
// speedup vs baseline: 1.0169x; 1.0169x over previous
#include <cuda_runtime.h>
#include <cuda_bf16.h>
#include <cstdint>

#define BHALF 4096
#define NROW  8192
#define DIM   256
#define INV_T (1.0f/0.07f)
#define LOG2E 1.4426950408889634f

#define TILE_M 128
#define SM_STRIDE 264            // 256 + 8 bf16 pad -> conflict-free LDSM phases
#define TILE_BYTES (TILE_M * SM_STRIDE * 2)          // 67584
#define SMEM_BYTES (3 * TILE_BYTES)                  // A + 2x B = 202752

#define NTILE 64                 // 8192 / 128
#define NPAIR 2080               // upper-triangle tile count
#define NTHREADS 512             // 16 warps, 4x4 warp grid, 32x32 per warp

__device__ __nv_bfloat16 g_zn[NROW * DIM];   // normalized rows, bf16 (4 MB)
__device__ float g_sumexp[NROW];
__device__ float g_pos[NROW];
__device__ volatile unsigned g_gen;          // grid-barrier generation
__device__ unsigned g_count;                 // grid-barrier arrivals
__device__ unsigned g_done;                  // tail election

// ---------------------------------------------------------------------------
// soft grid barrier (single-wave persistent grid only)
// ---------------------------------------------------------------------------
__device__ __forceinline__ void grid_barrier(unsigned nblk) {
    __threadfence();
    __syncthreads();
    if (threadIdx.x == 0) {
        unsigned gen = g_gen;
        if (atomicAdd(&g_count, 1) == nblk - 1) {
            g_count = 0;
            __threadfence();
            g_gen = gen + 1;
        } else {
            while (g_gen == gen) {}
            __threadfence();
        }
    }
    __syncthreads();
}

// ---------------------------------------------------------------------------
// fast exp via 2^y on the FMA pipe
// ---------------------------------------------------------------------------
__device__ __forceinline__ float fast_exp2(float y) {
    float t  = y + 12582912.0f;          // round-to-nearest-int trick (1.5*2^23)
    int   i  = __float_as_int(t);
    float nf = t - 12582912.0f;
    float f  = y - nf;                   // f in [-0.5, 0.5]
    float p  = fmaf(1.3333558e-3f, f, 9.6181291e-3f);
    p = fmaf(p, f, 5.5504109e-2f);
    p = fmaf(p, f, 2.4022651e-1f);
    p = fmaf(p, f, 6.9314718e-1f);
    p = fmaf(p, f, 1.0f);
    return p * __int_as_float((i << 23) + 0x3F800000);
}

__device__ __forceinline__ void mma16816(float c[4],
                                         unsigned a0, unsigned a1, unsigned a2, unsigned a3,
                                         unsigned b0, unsigned b1) {
    asm volatile(
        "mma.sync.aligned.m16n8k16.row.col.f32.bf16.bf16.f32 "
        "{%0,%1,%2,%3}, {%4,%5,%6,%7}, {%8,%9}, {%0,%1,%2,%3};\n"
        : "+f"(c[0]), "+f"(c[1]), "+f"(c[2]), "+f"(c[3])
        : "r"(a0), "r"(a1), "r"(a2), "r"(a3), "r"(b0), "r"(b1));
}

// ldmatrix x4: 4 8x8 b16 fragments; lane l supplies row (l&7) of matrix l>>3
__device__ __forceinline__ void ldsm_x4(unsigned* r, uint32_t addr) {
    asm volatile("ldmatrix.sync.aligned.m8n8.x4.shared.b16 {%0,%1,%2,%3}, [%4];"
                 : "=r"(r[0]), "=r"(r[1]), "=r"(r[2]), "=r"(r[3]) : "r"(addr));
}

__device__ __forceinline__ void cp_async16(void* smem_dst, const void* gsrc) {
    unsigned s = (unsigned)__cvta_generic_to_shared(smem_dst);
    asm volatile("cp.async.cg.shared.global [%0], [%1], 16;\n" :: "r"(s), "l"(gsrc));
}
__device__ __forceinline__ void cp_commit() {
    asm volatile("cp.async.commit_group;\n" ::: "memory");
}
__device__ __forceinline__ void cp_wait1() {
    asm volatile("cp.async.wait_group 1;\n" ::: "memory");
}
__device__ __forceinline__ void cp_wait0() {
    asm volatile("cp.async.wait_group 0;\n" ::: "memory");
}

__device__ __forceinline__ void load_tile_cp(__nv_bfloat16* dst,
                                             const __nv_bfloat16* src, int tid) {
    #pragma unroll
    for (int it = 0; it < 8; it++) {
        int idx = tid + it * NTHREADS;     // 4096 16B chunks
        int r = idx >> 5, c8 = idx & 31;
        cp_async16(dst + r * SM_STRIDE + c8 * 8, src + r * 256 + c8 * 8);
    }
}

__device__ __forceinline__ void load_tile_sync(__nv_bfloat16* dst,
                                               const __nv_bfloat16* src, int tid) {
    const uint4* gsrc = (const uint4*)src;
    #pragma unroll
    for (int it = 0; it < 8; it++) {
        int idx = tid + it * NTHREADS;
        int r = idx >> 5, c8 = idx & 31;
        *(uint4*)(dst + r * SM_STRIDE + c8 * 8) = gsrc[r * 32 + c8];
    }
}

// decode linear upper-triangle tile index q -> (i, j)
__device__ __forceinline__ void decode_tile(int q, int& i, int& j) {
    i = 0;
    int rem = q;
    while (rem >= NTILE - i) { rem -= NTILE - i; i++; }
    j = i + rem;
}

__device__ __forceinline__ void flush_rsum(float (&rsum)[2][2], int iT,
                                           int wm, int g, int tig) {
    #pragma unroll
    for (int mt = 0; mt < 2; mt++)
        #pragma unroll
        for (int h = 0; h < 2; h++) {
            float v = rsum[mt][h];
            v += __shfl_xor_sync(0xffffffffu, v, 1);
            v += __shfl_xor_sync(0xffffffffu, v, 2);
            if (tig == 0)
                atomicAdd(&g_sumexp[iT * TILE_M + wm * 32 + mt * 16 + g + h * 8], v);
            rsum[mt][h] = 0.0f;
        }
}

__device__ __forceinline__ void flush_csum(float (&csum)[4][2], int jP,
                                           int wn, int g, int tig) {
    #pragma unroll
    for (int nt = 0; nt < 4; nt++)
        #pragma unroll
        for (int p = 0; p < 2; p++) {
            float v = csum[nt][p];
            v += __shfl_xor_sync(0xffffffffu, v, 4);
            v += __shfl_xor_sync(0xffffffffu, v, 8);
            v += __shfl_xor_sync(0xffffffffu, v, 16);
            if (g == 0)
                atomicAdd(&g_sumexp[jP * TILE_M + wn * 32 + nt * 8 + tig * 2 + p], v);
        }
}

// ---------------------------------------------------------------------------
// one-warp row normalize
// ---------------------------------------------------------------------------
__device__ __forceinline__ void norm_row(int row, const float* __restrict__ z_i,
                                         const float* __restrict__ z_j, int lane) {
    const float* src = (row < BHALF) ? (z_i + (size_t)row * DIM)
                                     : (z_j + (size_t)(row - BHALF) * DIM);
    float4 v0 = ((const float4*)src)[lane * 2];
    float4 v1 = ((const float4*)src)[lane * 2 + 1];
    float ss = v0.x*v0.x + v0.y*v0.y + v0.z*v0.z + v0.w*v0.w
             + v1.x*v1.x + v1.y*v1.y + v1.z*v1.z + v1.w*v1.w;
    #pragma unroll
    for (int o = 16; o; o >>= 1) ss += __shfl_xor_sync(0xffffffffu, ss, o);
    float inv = 1.0f / fmaxf(sqrtf(ss), 1e-8f);

    __nv_bfloat162 h0 = __floats2bfloat162_rn(v0.x*inv, v0.y*inv);
    __nv_bfloat162 h1 = __floats2bfloat162_rn(v0.z*inv, v0.w*inv);
    __nv_bfloat162 h2 = __floats2bfloat162_rn(v1.x*inv, v1.y*inv);
    __nv_bfloat162 h3 = __floats2bfloat162_rn(v1.z*inv, v1.w*inv);
    uint4 u;
    u.x = *(unsigned*)&h0; u.y = *(unsigned*)&h1;
    u.z = *(unsigned*)&h2; u.w = *(unsigned*)&h3;
    *(uint4*)(g_zn + (size_t)row * DIM + lane * 8) = u;
    if (lane == 0) { g_sumexp[row] = 0.0f; g_pos[row] = 0.0f; }
}

// ---------------------------------------------------------------------------
// fused persistent kernel: normalize -> grid barrier -> symmetric GEMM with
// fused softmax-sum epilogue -> last-block loss tail.
// 512 threads, 4x4 warp grid, 32x32 warp tile, ldmatrix fragment loads.
// ---------------------------------------------------------------------------
__global__ void __launch_bounds__(NTHREADS) ntxent_fused_kernel(
    const float* __restrict__ z_i, const float* __restrict__ z_j,
    float* __restrict__ out)
{
    extern __shared__ __nv_bfloat16 smem[];
    __nv_bfloat16* As  = smem;
    __nv_bfloat16* Bs0 = smem + TILE_M * SM_STRIDE;
    __nv_bfloat16* Bs1 = Bs0 + TILE_M * SM_STRIDE;

    const int tid  = threadIdx.x;
    const int warp = tid >> 5, lane = tid & 31;
    const int g    = lane >> 2, tig = lane & 3;
    const int wm   = warp >> 2, wn = warp & 3;   // 4x4 grid -> 32x32 per warp
    const unsigned nblk = gridDim.x;

    // ---- phase 1: normalize ----
    {
        int stride = nblk * 16;
        for (int r0 = blockIdx.x * 16 + warp; r0 < NROW; r0 += 2 * stride) {
            int r1 = r0 + stride;
            norm_row(r0, z_i, z_j, lane);
            if (r1 < NROW) norm_row(r1, z_i, z_j, lane);
        }
    }

    grid_barrier(nblk);

    // ---- phase 2: GEMM over balanced contiguous triangle ranges ----
    int bid = blockIdx.x;
    int q0  = (int)(((long long)bid * NPAIR) / nblk);
    int q1  = (int)(((long long)(bid + 1) * NPAIR) / nblk);

    if (q0 < q1) {
        int iCur, jCur;
        decode_tile(q0, iCur, jCur);

        load_tile_sync(As, g_zn + (size_t)iCur * TILE_M * DIM, tid);
        int iLoaded = iCur;
        load_tile_cp(Bs0, g_zn + (size_t)jCur * TILE_M * DIM, tid);
        cp_commit();

        // per-lane LDSM base offsets (bytes): lane l -> row (base + (l&15)),
        // k-offset (l>>4)*8 bf16. x4 matrices = {rows 0-7 kLo, rows 8-15 kLo,
        // rows 0-7 kHi, rows 8-15 kHi} == mma fragment order.
        const uint32_t sAs = (uint32_t)__cvta_generic_to_shared(As);
        const uint32_t sB0 = (uint32_t)__cvta_generic_to_shared(Bs0);
        const uint32_t sB1 = (uint32_t)__cvta_generic_to_shared(Bs1);
        const uint32_t STEP16 = 16u * SM_STRIDE * 2u;          // 16 rows
        const uint32_t aOff = ((wm * 32 + (lane & 15)) * SM_STRIDE + (lane >> 4) * 8) * 2;
        const uint32_t bOff = ((wn * 32 + (lane & 15)) * SM_STRIDE + (lane >> 4) * 8) * 2;

        float rsum[2][2];
        rsum[0][0] = rsum[0][1] = rsum[1][0] = rsum[1][1] = 0.f;

        for (int q = q0; q < q1; q++) {
            int buf = (q - q0) & 1;
            int iN = iCur, jN = jCur + 1;
            if (jN == NTILE) { iN++; jN = iN; }

            __syncthreads();                    // prior tile fully consumed

            if (q + 1 < q1)
                load_tile_cp(buf ? Bs0 : Bs1, g_zn + (size_t)jN * TILE_M * DIM, tid);
            cp_commit();                        // uniform group count

            if (iCur != iLoaded) {
                flush_rsum(rsum, iLoaded, wm, g, tig);
                load_tile_sync(As, g_zn + (size_t)iCur * TILE_M * DIM, tid);
                iLoaded = iCur;
            }

            cp_wait1();
            __syncthreads();

            const uint32_t aA0 = sAs + aOff;
            const uint32_t aA1 = aA0 + STEP16;
            const uint32_t bB  = (buf ? sB1 : sB0) + bOff;
            const uint32_t bA1 = bB + STEP16;

            float acc[2][4][4];
            #pragma unroll
            for (int mt = 0; mt < 2; mt++)
                #pragma unroll
                for (int nt = 0; nt < 4; nt++)
                    #pragma unroll
                    for (int ci = 0; ci < 4; ci++) acc[mt][nt][ci] = 0.f;

            #pragma unroll
            for (int kk = 0; kk < 16; kk++) {
                const uint32_t kb = kk * 32u;   // 16 bf16 = 32 bytes per K-step
                unsigned af0[4], af1[4], bf0[4], bf1[4];
                ldsm_x4(af0, aA0 + kb);         // A rows wm*32+0..15
                ldsm_x4(af1, aA1 + kb);         // A rows wm*32+16..31
                ldsm_x4(bf0, bB  + kb);         // B cols wn*32+0..15
                ldsm_x4(bf1, bA1 + kb);         // B cols wn*32+16..31

                // bfX = { nt_lo kLo, nt_hi kLo, nt_lo kHi, nt_hi kHi }
                mma16816(acc[0][0], af0[0], af0[1], af0[2], af0[3], bf0[0], bf0[2]);
                mma16816(acc[0][1], af0[0], af0[1], af0[2], af0[3], bf0[1], bf0[3]);
                mma16816(acc[0][2], af0[0], af0[1], af0[2], af0[3], bf1[0], bf1[2]);
                mma16816(acc[0][3], af0[0], af0[1], af0[2], af0[3], bf1[1], bf1[3]);
                mma16816(acc[1][0], af1[0], af1[1], af1[2], af1[3], bf0[0], bf0[2]);
                mma16816(acc[1][1], af1[0], af1[1], af1[2], af1[3], bf0[1], bf0[3]);
                mma16816(acc[1][2], af1[0], af1[1], af1[2], af1[3], bf1[0], bf1[2]);
                mma16816(acc[1][3], af1[0], af1[1], af1[2], af1[3], bf1[1], bf1[3]);
            }

            // ---- fused epilogue ----
            const bool diag = (jCur == iCur);
            const bool pos  = (jCur == iCur + 32);
            float csum[4][2];
            #pragma unroll
            for (int nt = 0; nt < 4; nt++) { csum[nt][0] = 0.f; csum[nt][1] = 0.f; }

            #pragma unroll
            for (int mt = 0; mt < 2; mt++)
                #pragma unroll
                for (int nt = 0; nt < 4; nt++)
                    #pragma unroll
                    for (int ci = 0; ci < 4; ci++) {
                        float v = acc[mt][nt][ci];
                        float e = fast_exp2(v * (INV_T * LOG2E));
                        if (diag | pos) {
                            int row = iCur * TILE_M + wm * 32 + mt * 16 + g + (ci >> 1) * 8;
                            int col = jCur * TILE_M + wn * 32 + nt * 8 + tig * 2 + (ci & 1);
                            if (pos & (col == row + BHALF)) {
                                float pv = v * INV_T;
                                g_pos[row] = pv;
                                g_pos[col] = pv;
                            }
                            if (diag & (col == row)) e = 0.0f;
                        }
                        rsum[mt][ci >> 1] += e;
                        csum[nt][ci & 1]  += e;
                    }

            if (!diag) flush_csum(csum, jCur, wn, g, tig);

            iCur = iN; jCur = jN;
        }

        flush_rsum(rsum, iLoaded, wm, g, tig);
        cp_wait0();
    }

    // ---- phase 3: last block computes the loss ----
    __threadfence();
    __syncthreads();
    __shared__ unsigned amLast;
    if (tid == 0)
        amLast = (atomicAdd(&g_done, 1) == nblk - 1) ? 1u : 0u;
    __syncthreads();

    if (amLast) {
        __threadfence();
        float s = 0.0f;
        for (int k = tid; k < NROW; k += NTHREADS)
            s += logf(__ldcg(&g_sumexp[k])) - __ldcg(&g_pos[k]);
        #pragma unroll
        for (int o = 16; o; o >>= 1) s += __shfl_xor_sync(0xffffffffu, s, o);
        __shared__ float sw[16];
        if (lane == 0) sw[warp] = s;
        __syncthreads();
        if (tid == 0) {
            float v = 0.0f;
            #pragma unroll
            for (int w = 0; w < 16; w++) v += sw[w];
            out[0] = v / (float)NROW;
            g_done = 0;              // reset for next graph replay
        }
    }
}

extern "C" void kernel_launch(void* const* d_in, const int* in_sizes, int n_in,
                              void* d_out, int out_size) {
    const float* z_i = (const float*)d_in[0];
    const float* z_j = (const float*)d_in[1];
    float* out = (float*)d_out;

    int dev = 0, nsm = 148;
    cudaGetDevice(&dev);
    cudaDeviceGetAttribute(&nsm, cudaDevAttrMultiProcessorCount, dev);
    if (nsm < 1) nsm = 148;
    if (nsm > 512) nsm = 512;

    cudaFuncSetAttribute(ntxent_fused_kernel,
                         cudaFuncAttributeMaxDynamicSharedMemorySize, SMEM_BYTES);

    ntxent_fused_kernel<<<nsm, NTHREADS, SMEM_BYTES>>>(z_i, z_j, out);
}

// round 11
// speedup vs baseline: 1.0433x; 1.0259x over previous
#include <cuda_runtime.h>
#include <cuda_bf16.h>
#include <cuda_fp16.h>
#include <cstdint>

#define BHALF 4096
#define NROW  8192
#define DIM   256
#define INV_T (1.0f/0.07f)
#define LOG2E 1.4426950408889634f

#define TILE_M 128
#define SM_STRIDE 264            // 256 + 8 fp16 pad -> conflict-free LDSM phases
#define TILE_BYTES (TILE_M * SM_STRIDE * 2)          // 67584
#define SMEM_BYTES (3 * TILE_BYTES)                  // A + 2x B = 202752

#define NTILE 64                 // 8192 / 128
#define NPAIR 2080               // upper-triangle tile count
#define NTHREADS 512             // 16 warps, 4x4 warp grid, 32x32 per warp

__device__ __half g_zn[NROW * DIM];          // normalized rows, fp16 (4 MB)
__device__ float g_sumexp[NROW];
__device__ float g_pos[NROW];
__device__ volatile unsigned g_gen;          // grid-barrier generation
__device__ unsigned g_count;                 // grid-barrier arrivals
__device__ unsigned g_done;                  // tail election

// ---------------------------------------------------------------------------
// soft grid barrier (single-wave persistent grid only)
// ---------------------------------------------------------------------------
__device__ __forceinline__ void grid_barrier(unsigned nblk) {
    __threadfence();
    __syncthreads();
    if (threadIdx.x == 0) {
        unsigned gen = g_gen;
        if (atomicAdd(&g_count, 1) == nblk - 1) {
            g_count = 0;
            __threadfence();
            g_gen = gen + 1;
        } else {
            while (g_gen == gen) {}
            __threadfence();
        }
    }
    __syncthreads();
}

// ---------------------------------------------------------------------------
// fast exp via 2^y on the FMA pipe
// ---------------------------------------------------------------------------
__device__ __forceinline__ float fast_exp2(float y) {
    float t  = y + 12582912.0f;          // round-to-nearest-int trick (1.5*2^23)
    int   i  = __float_as_int(t);
    float nf = t - 12582912.0f;
    float f  = y - nf;                   // f in [-0.5, 0.5]
    float p  = fmaf(1.3333558e-3f, f, 9.6181291e-3f);
    p = fmaf(p, f, 5.5504109e-2f);
    p = fmaf(p, f, 2.4022651e-1f);
    p = fmaf(p, f, 6.9314718e-1f);
    p = fmaf(p, f, 1.0f);
    return p * __int_as_float((i << 23) + 0x3F800000);
}

// fp16-accumulate HMMA: D,C are 2 regs (4 halves)
// reg0 = {row g,   col tig*2 / tig*2+1}
// reg1 = {row g+8, col tig*2 / tig*2+1}
__device__ __forceinline__ void mma_f16(unsigned c[2],
                                        unsigned a0, unsigned a1, unsigned a2, unsigned a3,
                                        unsigned b0, unsigned b1) {
    asm volatile(
        "mma.sync.aligned.m16n8k16.row.col.f16.f16.f16.f16 "
        "{%0,%1}, {%2,%3,%4,%5}, {%6,%7}, {%0,%1};\n"
        : "+r"(c[0]), "+r"(c[1])
        : "r"(a0), "r"(a1), "r"(a2), "r"(a3), "r"(b0), "r"(b1));
}

// ldmatrix x4: 4 8x8 b16 fragments
__device__ __forceinline__ void ldsm_x4(unsigned* r, uint32_t addr) {
    asm volatile("ldmatrix.sync.aligned.m8n8.x4.shared.b16 {%0,%1,%2,%3}, [%4];"
                 : "=r"(r[0]), "=r"(r[1]), "=r"(r[2]), "=r"(r[3]) : "r"(addr));
}

__device__ __forceinline__ void cp_async16(void* smem_dst, const void* gsrc) {
    unsigned s = (unsigned)__cvta_generic_to_shared(smem_dst);
    asm volatile("cp.async.cg.shared.global [%0], [%1], 16;\n" :: "r"(s), "l"(gsrc));
}
__device__ __forceinline__ void cp_commit() {
    asm volatile("cp.async.commit_group;\n" ::: "memory");
}
__device__ __forceinline__ void cp_wait1() {
    asm volatile("cp.async.wait_group 1;\n" ::: "memory");
}
__device__ __forceinline__ void cp_wait0() {
    asm volatile("cp.async.wait_group 0;\n" ::: "memory");
}

__device__ __forceinline__ void load_tile_cp(__half* dst,
                                             const __half* src, int tid) {
    #pragma unroll
    for (int it = 0; it < 8; it++) {
        int idx = tid + it * NTHREADS;     // 4096 16B chunks
        int r = idx >> 5, c8 = idx & 31;
        cp_async16(dst + r * SM_STRIDE + c8 * 8, src + r * 256 + c8 * 8);
    }
}

__device__ __forceinline__ void load_tile_sync(__half* dst,
                                               const __half* src, int tid) {
    const uint4* gsrc = (const uint4*)src;
    #pragma unroll
    for (int it = 0; it < 8; it++) {
        int idx = tid + it * NTHREADS;
        int r = idx >> 5, c8 = idx & 31;
        *(uint4*)(dst + r * SM_STRIDE + c8 * 8) = gsrc[r * 32 + c8];
    }
}

// decode linear upper-triangle tile index q -> (i, j)
__device__ __forceinline__ void decode_tile(int q, int& i, int& j) {
    i = 0;
    int rem = q;
    while (rem >= NTILE - i) { rem -= NTILE - i; i++; }
    j = i + rem;
}

__device__ __forceinline__ void flush_rsum(float (&rsum)[2][2], int iT,
                                           int wm, int g, int tig) {
    #pragma unroll
    for (int mt = 0; mt < 2; mt++)
        #pragma unroll
        for (int h = 0; h < 2; h++) {
            float v = rsum[mt][h];
            v += __shfl_xor_sync(0xffffffffu, v, 1);
            v += __shfl_xor_sync(0xffffffffu, v, 2);
            if (tig == 0)
                atomicAdd(&g_sumexp[iT * TILE_M + wm * 32 + mt * 16 + g + h * 8], v);
            rsum[mt][h] = 0.0f;
        }
}

__device__ __forceinline__ void flush_csum(float (&csum)[4][2], int jP,
                                           int wn, int g, int tig) {
    #pragma unroll
    for (int nt = 0; nt < 4; nt++)
        #pragma unroll
        for (int p = 0; p < 2; p++) {
            float v = csum[nt][p];
            v += __shfl_xor_sync(0xffffffffu, v, 4);
            v += __shfl_xor_sync(0xffffffffu, v, 8);
            v += __shfl_xor_sync(0xffffffffu, v, 16);
            if (g == 0)
                atomicAdd(&g_sumexp[jP * TILE_M + wn * 32 + nt * 8 + tig * 2 + p], v);
        }
}

// ---------------------------------------------------------------------------
// one-warp row normalize -> fp16
// ---------------------------------------------------------------------------
__device__ __forceinline__ void norm_row(int row, const float* __restrict__ z_i,
                                         const float* __restrict__ z_j, int lane) {
    const float* src = (row < BHALF) ? (z_i + (size_t)row * DIM)
                                     : (z_j + (size_t)(row - BHALF) * DIM);
    float4 v0 = ((const float4*)src)[lane * 2];
    float4 v1 = ((const float4*)src)[lane * 2 + 1];
    float ss = v0.x*v0.x + v0.y*v0.y + v0.z*v0.z + v0.w*v0.w
             + v1.x*v1.x + v1.y*v1.y + v1.z*v1.z + v1.w*v1.w;
    #pragma unroll
    for (int o = 16; o; o >>= 1) ss += __shfl_xor_sync(0xffffffffu, ss, o);
    float inv = 1.0f / fmaxf(sqrtf(ss), 1e-8f);

    __half2 h0 = __floats2half2_rn(v0.x*inv, v0.y*inv);
    __half2 h1 = __floats2half2_rn(v0.z*inv, v0.w*inv);
    __half2 h2 = __floats2half2_rn(v1.x*inv, v1.y*inv);
    __half2 h3 = __floats2half2_rn(v1.z*inv, v1.w*inv);
    uint4 u;
    u.x = *(unsigned*)&h0; u.y = *(unsigned*)&h1;
    u.z = *(unsigned*)&h2; u.w = *(unsigned*)&h3;
    *(uint4*)(g_zn + (size_t)row * DIM + lane * 8) = u;
    if (lane == 0) { g_sumexp[row] = 0.0f; g_pos[row] = 0.0f; }
}

// ---------------------------------------------------------------------------
// fused persistent kernel: normalize -> grid barrier -> symmetric GEMM with
// fused softmax-sum epilogue -> last-block loss tail.
// fp16 inputs + fp16 accumulation (tests the fp32-accum de-rate hypothesis).
// ---------------------------------------------------------------------------
__global__ void __launch_bounds__(NTHREADS) ntxent_fused_kernel(
    const float* __restrict__ z_i, const float* __restrict__ z_j,
    float* __restrict__ out)
{
    extern __shared__ __half smem[];
    __half* As  = smem;
    __half* Bs0 = smem + TILE_M * SM_STRIDE;
    __half* Bs1 = Bs0 + TILE_M * SM_STRIDE;

    const int tid  = threadIdx.x;
    const int warp = tid >> 5, lane = tid & 31;
    const int g    = lane >> 2, tig = lane & 3;
    const int wm   = warp >> 2, wn = warp & 3;   // 4x4 grid -> 32x32 per warp
    const unsigned nblk = gridDim.x;

    // ---- phase 1: normalize ----
    {
        int stride = nblk * 16;
        for (int r0 = blockIdx.x * 16 + warp; r0 < NROW; r0 += 2 * stride) {
            int r1 = r0 + stride;
            norm_row(r0, z_i, z_j, lane);
            if (r1 < NROW) norm_row(r1, z_i, z_j, lane);
        }
    }

    grid_barrier(nblk);

    // ---- phase 2: GEMM over balanced contiguous triangle ranges ----
    int bid = blockIdx.x;
    int q0  = (int)(((long long)bid * NPAIR) / nblk);
    int q1  = (int)(((long long)(bid + 1) * NPAIR) / nblk);

    if (q0 < q1) {
        int iCur, jCur;
        decode_tile(q0, iCur, jCur);

        load_tile_sync(As, g_zn + (size_t)iCur * TILE_M * DIM, tid);
        int iLoaded = iCur;
        load_tile_cp(Bs0, g_zn + (size_t)jCur * TILE_M * DIM, tid);
        cp_commit();

        const uint32_t sAs = (uint32_t)__cvta_generic_to_shared(As);
        const uint32_t sB0 = (uint32_t)__cvta_generic_to_shared(Bs0);
        const uint32_t sB1 = (uint32_t)__cvta_generic_to_shared(Bs1);
        const uint32_t STEP16 = 16u * SM_STRIDE * 2u;          // 16 rows
        const uint32_t aOff = ((wm * 32 + (lane & 15)) * SM_STRIDE + (lane >> 4) * 8) * 2;
        const uint32_t bOff = ((wn * 32 + (lane & 15)) * SM_STRIDE + (lane >> 4) * 8) * 2;

        float rsum[2][2];
        rsum[0][0] = rsum[0][1] = rsum[1][0] = rsum[1][1] = 0.f;

        for (int q = q0; q < q1; q++) {
            int buf = (q - q0) & 1;
            int iN = iCur, jN = jCur + 1;
            if (jN == NTILE) { iN++; jN = iN; }

            __syncthreads();                    // prior tile fully consumed

            if (q + 1 < q1)
                load_tile_cp(buf ? Bs0 : Bs1, g_zn + (size_t)jN * TILE_M * DIM, tid);
            cp_commit();                        // uniform group count

            if (iCur != iLoaded) {
                flush_rsum(rsum, iLoaded, wm, g, tig);
                load_tile_sync(As, g_zn + (size_t)iCur * TILE_M * DIM, tid);
                iLoaded = iCur;
            }

            cp_wait1();
            __syncthreads();

            const uint32_t aA0 = sAs + aOff;
            const uint32_t aA1 = aA0 + STEP16;
            const uint32_t bB  = (buf ? sB1 : sB0) + bOff;
            const uint32_t bA1 = bB + STEP16;

            unsigned acc[2][4][2];
            #pragma unroll
            for (int mt = 0; mt < 2; mt++)
                #pragma unroll
                for (int nt = 0; nt < 4; nt++) {
                    acc[mt][nt][0] = 0u; acc[mt][nt][1] = 0u;
                }

            #pragma unroll
            for (int kk = 0; kk < 16; kk++) {
                const uint32_t kb = kk * 32u;   // 16 fp16 = 32 bytes per K-step
                unsigned af0[4], af1[4], bf0[4], bf1[4];
                ldsm_x4(af0, aA0 + kb);         // A rows wm*32+0..15
                ldsm_x4(af1, aA1 + kb);         // A rows wm*32+16..31
                ldsm_x4(bf0, bB  + kb);         // B cols wn*32+0..15
                ldsm_x4(bf1, bA1 + kb);         // B cols wn*32+16..31

                mma_f16(acc[0][0], af0[0], af0[1], af0[2], af0[3], bf0[0], bf0[2]);
                mma_f16(acc[0][1], af0[0], af0[1], af0[2], af0[3], bf0[1], bf0[3]);
                mma_f16(acc[0][2], af0[0], af0[1], af0[2], af0[3], bf1[0], bf1[2]);
                mma_f16(acc[0][3], af0[0], af0[1], af0[2], af0[3], bf1[1], bf1[3]);
                mma_f16(acc[1][0], af1[0], af1[1], af1[2], af1[3], bf0[0], bf0[2]);
                mma_f16(acc[1][1], af1[0], af1[1], af1[2], af1[3], bf0[1], bf0[3]);
                mma_f16(acc[1][2], af1[0], af1[1], af1[2], af1[3], bf1[0], bf1[2]);
                mma_f16(acc[1][3], af1[0], af1[1], af1[2], af1[3], bf1[1], bf1[3]);
            }

            // ---- fused epilogue ----
            const bool diag = (jCur == iCur);
            const bool pos  = (jCur == iCur + 32);
            float csum[4][2];
            #pragma unroll
            for (int nt = 0; nt < 4; nt++) { csum[nt][0] = 0.f; csum[nt][1] = 0.f; }

            #pragma unroll
            for (int mt = 0; mt < 2; mt++)
                #pragma unroll
                for (int nt = 0; nt < 4; nt++)
                    #pragma unroll
                    for (int h = 0; h < 2; h++) {
                        __half2 hv = *reinterpret_cast<__half2*>(&acc[mt][nt][h]);
                        float v0 = __low2float(hv);
                        float v1 = __high2float(hv);
                        float e0 = fast_exp2(v0 * (INV_T * LOG2E));
                        float e1 = fast_exp2(v1 * (INV_T * LOG2E));
                        if (diag | pos) {
                            int row = iCur * TILE_M + wm * 32 + mt * 16 + g + h * 8;
                            int col = jCur * TILE_M + wn * 32 + nt * 8 + tig * 2;
                            if (pos) {
                                if (col == row + BHALF) {
                                    float pv = v0 * INV_T;
                                    g_pos[row] = pv; g_pos[col] = pv;
                                }
                                if (col + 1 == row + BHALF) {
                                    float pv = v1 * INV_T;
                                    g_pos[row] = pv; g_pos[col + 1] = pv;
                                }
                            }
                            if (diag) {
                                if (col == row)     e0 = 0.0f;
                                if (col + 1 == row) e1 = 0.0f;
                            }
                        }
                        rsum[mt][h] += e0 + e1;
                        csum[nt][0] += e0;
                        csum[nt][1] += e1;
                    }

            if (!diag) flush_csum(csum, jCur, wn, g, tig);

            iCur = iN; jCur = jN;
        }

        flush_rsum(rsum, iLoaded, wm, g, tig);
        cp_wait0();
    }

    // ---- phase 3: last block computes the loss ----
    __threadfence();
    __syncthreads();
    __shared__ unsigned amLast;
    if (tid == 0)
        amLast = (atomicAdd(&g_done, 1) == nblk - 1) ? 1u : 0u;
    __syncthreads();

    if (amLast) {
        __threadfence();
        float s = 0.0f;
        for (int k = tid; k < NROW; k += NTHREADS)
            s += logf(__ldcg(&g_sumexp[k])) - __ldcg(&g_pos[k]);
        #pragma unroll
        for (int o = 16; o; o >>= 1) s += __shfl_xor_sync(0xffffffffu, s, o);
        __shared__ float sw[16];
        if (lane == 0) sw[warp] = s;
        __syncthreads();
        if (tid == 0) {
            float v = 0.0f;
            #pragma unroll
            for (int w = 0; w < 16; w++) v += sw[w];
            out[0] = v / (float)NROW;
            g_done = 0;              // reset for next graph replay
        }
    }
}

extern "C" void kernel_launch(void* const* d_in, const int* in_sizes, int n_in,
                              void* d_out, int out_size) {
    const float* z_i = (const float*)d_in[0];
    const float* z_j = (const float*)d_in[1];
    float* out = (float*)d_out;

    int dev = 0, nsm = 148;
    cudaGetDevice(&dev);
    cudaDeviceGetAttribute(&nsm, cudaDevAttrMultiProcessorCount, dev);
    if (nsm < 1) nsm = 148;
    if (nsm > 512) nsm = 512;

    cudaFuncSetAttribute(ntxent_fused_kernel,
                         cudaFuncAttributeMaxDynamicSharedMemorySize, SMEM_BYTES);

    ntxent_fused_kernel<<<nsm, NTHREADS, SMEM_BYTES>>>(z_i, z_j, out);
}

// round 12
// speedup vs baseline: 1.0440x; 1.0007x over previous
#include <cuda_runtime.h>
#include <cuda_bf16.h>
#include <cuda_fp16.h>
#include <cstdint>

#define BHALF 4096
#define NROW  8192
#define DIM   256
#define INV_T (1.0f/0.07f)
#define LOG2E 1.4426950408889634f

#define TILE_M 128
#define SM_STRIDE 264            // 256 + 8 fp16 pad -> conflict-free LDSM phases
#define TILE_BYTES (TILE_M * SM_STRIDE * 2)          // 67584
#define SMEM_BYTES (3 * TILE_BYTES)                  // A + 2x B = 202752

#define NTILE 64                 // 8192 / 128
#define NPAIR 2080               // upper-triangle tile count
#define NTHREADS 512             // 16 warps, 4x4 warp grid, 32x32 per warp

__device__ __half g_zn[NROW * DIM];          // normalized rows, fp16 (4 MB)
__device__ float g_sumexp[NROW];
__device__ float g_pos[NROW];
__device__ volatile unsigned g_gen;          // grid-barrier generation
__device__ unsigned g_count;                 // grid-barrier arrivals
__device__ unsigned g_done;                  // tail election

// ---------------------------------------------------------------------------
// soft grid barrier (single-wave persistent grid only)
// ---------------------------------------------------------------------------
__device__ __forceinline__ void grid_barrier(unsigned nblk) {
    __threadfence();
    __syncthreads();
    if (threadIdx.x == 0) {
        unsigned gen = g_gen;
        if (atomicAdd(&g_count, 1) == nblk - 1) {
            g_count = 0;
            __threadfence();
            g_gen = gen + 1;
        } else {
            while (g_gen == gen) {}
            __threadfence();
        }
    }
    __syncthreads();
}

// ---------------------------------------------------------------------------
// fast exp via 2^y on the FMA pipe
// ---------------------------------------------------------------------------
__device__ __forceinline__ float fast_exp2(float y) {
    float t  = y + 12582912.0f;          // round-to-nearest-int trick (1.5*2^23)
    int   i  = __float_as_int(t);
    float nf = t - 12582912.0f;
    float f  = y - nf;                   // f in [-0.5, 0.5]
    float p  = fmaf(1.3333558e-3f, f, 9.6181291e-3f);
    p = fmaf(p, f, 5.5504109e-2f);
    p = fmaf(p, f, 2.4022651e-1f);
    p = fmaf(p, f, 6.9314718e-1f);
    p = fmaf(p, f, 1.0f);
    return p * __int_as_float((i << 23) + 0x3F800000);
}

// fp16-accumulate HMMA: D,C are 2 regs (4 halves)
__device__ __forceinline__ void mma_f16(unsigned c[2],
                                        unsigned a0, unsigned a1, unsigned a2, unsigned a3,
                                        unsigned b0, unsigned b1) {
    asm volatile(
        "mma.sync.aligned.m16n8k16.row.col.f16.f16.f16.f16 "
        "{%0,%1}, {%2,%3,%4,%5}, {%6,%7}, {%0,%1};\n"
        : "+r"(c[0]), "+r"(c[1])
        : "r"(a0), "r"(a1), "r"(a2), "r"(a3), "r"(b0), "r"(b1));
}

__device__ __forceinline__ void ldsm_x4(unsigned* r, uint32_t addr) {
    asm volatile("ldmatrix.sync.aligned.m8n8.x4.shared.b16 {%0,%1,%2,%3}, [%4];"
                 : "=r"(r[0]), "=r"(r[1]), "=r"(r[2]), "=r"(r[3]) : "r"(addr));
}

__device__ __forceinline__ void cp_async16(void* smem_dst, const void* gsrc) {
    unsigned s = (unsigned)__cvta_generic_to_shared(smem_dst);
    asm volatile("cp.async.cg.shared.global [%0], [%1], 16;\n" :: "r"(s), "l"(gsrc));
}
__device__ __forceinline__ void cp_commit() {
    asm volatile("cp.async.commit_group;\n" ::: "memory");
}
__device__ __forceinline__ void cp_wait1() {
    asm volatile("cp.async.wait_group 1;\n" ::: "memory");
}
__device__ __forceinline__ void cp_wait0() {
    asm volatile("cp.async.wait_group 0;\n" ::: "memory");
}

__device__ __forceinline__ void load_tile_cp(__half* dst,
                                             const __half* src, int tid) {
    #pragma unroll
    for (int it = 0; it < 8; it++) {
        int idx = tid + it * NTHREADS;     // 4096 16B chunks
        int r = idx >> 5, c8 = idx & 31;
        cp_async16(dst + r * SM_STRIDE + c8 * 8, src + r * 256 + c8 * 8);
    }
}

__device__ __forceinline__ void load_tile_sync(__half* dst,
                                               const __half* src, int tid) {
    const uint4* gsrc = (const uint4*)src;
    #pragma unroll
    for (int it = 0; it < 8; it++) {
        int idx = tid + it * NTHREADS;
        int r = idx >> 5, c8 = idx & 31;
        *(uint4*)(dst + r * SM_STRIDE + c8 * 8) = gsrc[r * 32 + c8];
    }
}

// decode linear upper-triangle tile index q -> (i, j)
__device__ __forceinline__ void decode_tile(int q, int& i, int& j) {
    i = 0;
    int rem = q;
    while (rem >= NTILE - i) { rem -= NTILE - i; i++; }
    j = i + rem;
}

__device__ __forceinline__ void flush_rsum(float (&rsum)[2][2], int iT,
                                           int wm, int g, int tig) {
    #pragma unroll
    for (int mt = 0; mt < 2; mt++)
        #pragma unroll
        for (int h = 0; h < 2; h++) {
            float v = rsum[mt][h];
            v += __shfl_xor_sync(0xffffffffu, v, 1);
            v += __shfl_xor_sync(0xffffffffu, v, 2);
            if (tig == 0)
                atomicAdd(&g_sumexp[iT * TILE_M + wm * 32 + mt * 16 + g + h * 8], v);
            rsum[mt][h] = 0.0f;
        }
}

__device__ __forceinline__ void flush_csum(float (&csum)[4][2], int jP,
                                           int wn, int g, int tig) {
    #pragma unroll
    for (int nt = 0; nt < 4; nt++)
        #pragma unroll
        for (int p = 0; p < 2; p++) {
            float v = csum[nt][p];
            v += __shfl_xor_sync(0xffffffffu, v, 4);
            v += __shfl_xor_sync(0xffffffffu, v, 8);
            v += __shfl_xor_sync(0xffffffffu, v, 16);
            if (g == 0)
                atomicAdd(&g_sumexp[jP * TILE_M + wn * 32 + nt * 8 + tig * 2 + p], v);
        }
}

// ---------------------------------------------------------------------------
// one-warp row normalize -> fp16
// ---------------------------------------------------------------------------
__device__ __forceinline__ void norm_row(int row, const float* __restrict__ z_i,
                                         const float* __restrict__ z_j, int lane) {
    const float* src = (row < BHALF) ? (z_i + (size_t)row * DIM)
                                     : (z_j + (size_t)(row - BHALF) * DIM);
    float4 v0 = ((const float4*)src)[lane * 2];
    float4 v1 = ((const float4*)src)[lane * 2 + 1];
    float ss = v0.x*v0.x + v0.y*v0.y + v0.z*v0.z + v0.w*v0.w
             + v1.x*v1.x + v1.y*v1.y + v1.z*v1.z + v1.w*v1.w;
    #pragma unroll
    for (int o = 16; o; o >>= 1) ss += __shfl_xor_sync(0xffffffffu, ss, o);
    float inv = 1.0f / fmaxf(sqrtf(ss), 1e-8f);

    __half2 h0 = __floats2half2_rn(v0.x*inv, v0.y*inv);
    __half2 h1 = __floats2half2_rn(v0.z*inv, v0.w*inv);
    __half2 h2 = __floats2half2_rn(v1.x*inv, v1.y*inv);
    __half2 h3 = __floats2half2_rn(v1.z*inv, v1.w*inv);
    uint4 u;
    u.x = *(unsigned*)&h0; u.y = *(unsigned*)&h1;
    u.z = *(unsigned*)&h2; u.w = *(unsigned*)&h3;
    *(uint4*)(g_zn + (size_t)row * DIM + lane * 8) = u;
    if (lane == 0) { g_sumexp[row] = 0.0f; g_pos[row] = 0.0f; }
}

// ---------------------------------------------------------------------------
// MMA over current tile with (a) LDSM double-buffering and (b) epilogue of
// previous tile (iP,jP) interleaved: kk-step kk handles prev half2 index
// (mt=kk>>3, nt=(kk>>1)&3, h=kk&1).
// ---------------------------------------------------------------------------
__device__ __forceinline__ void mma_tile_f16(
    uint32_t aA0, uint32_t aA1, uint32_t bB0, uint32_t bB1,
    unsigned (&cur)[2][4][2], unsigned (&prev)[2][4][2],
    bool havePrev, int iP, int jP, float (&rsum)[2][2],
    int wm, int wn, int g, int tig)
{
    float csum[4][2];
    #pragma unroll
    for (int nt = 0; nt < 4; nt++) { csum[nt][0] = 0.f; csum[nt][1] = 0.f; }
    #pragma unroll
    for (int mt = 0; mt < 2; mt++)
        #pragma unroll
        for (int nt = 0; nt < 4; nt++) { cur[mt][nt][0] = 0u; cur[mt][nt][1] = 0u; }

    const bool diag = (iP == jP);
    const bool pos  = (jP == iP + 32);

    unsigned fa0[2][4], fa1[2][4], fb0[2][4], fb1[2][4];
    ldsm_x4(fa0[0], aA0);
    ldsm_x4(fa1[0], aA1);
    ldsm_x4(fb0[0], bB0);
    ldsm_x4(fb1[0], bB1);

    #pragma unroll
    for (int kk = 0; kk < 16; kk++) {
        const int c = kk & 1, n = c ^ 1;
        if (kk < 15) {                       // prefetch kk+1 fragments
            const uint32_t kb = (uint32_t)(kk + 1) * 32u;
            ldsm_x4(fa0[n], aA0 + kb);
            ldsm_x4(fa1[n], aA1 + kb);
            ldsm_x4(fb0[n], bB0 + kb);
            ldsm_x4(fb1[n], bB1 + kb);
        }

        mma_f16(cur[0][0], fa0[c][0], fa0[c][1], fa0[c][2], fa0[c][3], fb0[c][0], fb0[c][2]);
        mma_f16(cur[0][1], fa0[c][0], fa0[c][1], fa0[c][2], fa0[c][3], fb0[c][1], fb0[c][3]);
        mma_f16(cur[0][2], fa0[c][0], fa0[c][1], fa0[c][2], fa0[c][3], fb1[c][0], fb1[c][2]);
        mma_f16(cur[0][3], fa0[c][0], fa0[c][1], fa0[c][2], fa0[c][3], fb1[c][1], fb1[c][3]);
        mma_f16(cur[1][0], fa1[c][0], fa1[c][1], fa1[c][2], fa1[c][3], fb0[c][0], fb0[c][2]);
        mma_f16(cur[1][1], fa1[c][0], fa1[c][1], fa1[c][2], fa1[c][3], fb0[c][1], fb0[c][3]);
        mma_f16(cur[1][2], fa1[c][0], fa1[c][1], fa1[c][2], fa1[c][3], fb1[c][0], fb1[c][2]);
        mma_f16(cur[1][3], fa1[c][0], fa1[c][1], fa1[c][2], fa1[c][3], fb1[c][1], fb1[c][3]);

        if (havePrev) {                      // interleaved prev-tile epilogue
            const int mt = kk >> 3, nt = (kk >> 1) & 3, h = kk & 1;
            __half2 hv = *reinterpret_cast<__half2*>(&prev[mt][nt][h]);
            float v0 = __low2float(hv), v1 = __high2float(hv);
            float e0 = fast_exp2(v0 * (INV_T * LOG2E));
            float e1 = fast_exp2(v1 * (INV_T * LOG2E));
            if (diag | pos) {
                int row = iP * TILE_M + wm * 32 + mt * 16 + g + h * 8;
                int col = jP * TILE_M + wn * 32 + nt * 8 + tig * 2;
                if (pos) {
                    if (col == row + BHALF) {
                        float pv = v0 * INV_T; g_pos[row] = pv; g_pos[col] = pv;
                    }
                    if (col + 1 == row + BHALF) {
                        float pv = v1 * INV_T; g_pos[row] = pv; g_pos[col + 1] = pv;
                    }
                }
                if (diag) {
                    if (col == row)     e0 = 0.0f;
                    if (col + 1 == row) e1 = 0.0f;
                }
            }
            rsum[mt][h] += e0 + e1;
            csum[nt][0] += e0;
            csum[nt][1] += e1;
        }
    }

    if (havePrev && !diag) flush_csum(csum, jP, wn, g, tig);
}

// standalone epilogue for the final tile of a block's range
__device__ __forceinline__ void epi_tile_f16(
    unsigned (&prev)[2][4][2], int iP, int jP, float (&rsum)[2][2],
    int wm, int wn, int g, int tig)
{
    float csum[4][2];
    #pragma unroll
    for (int nt = 0; nt < 4; nt++) { csum[nt][0] = 0.f; csum[nt][1] = 0.f; }
    const bool diag = (iP == jP);
    const bool pos  = (jP == iP + 32);
    #pragma unroll
    for (int mt = 0; mt < 2; mt++)
        #pragma unroll
        for (int nt = 0; nt < 4; nt++)
            #pragma unroll
            for (int h = 0; h < 2; h++) {
                __half2 hv = *reinterpret_cast<__half2*>(&prev[mt][nt][h]);
                float v0 = __low2float(hv), v1 = __high2float(hv);
                float e0 = fast_exp2(v0 * (INV_T * LOG2E));
                float e1 = fast_exp2(v1 * (INV_T * LOG2E));
                if (diag | pos) {
                    int row = iP * TILE_M + wm * 32 + mt * 16 + g + h * 8;
                    int col = jP * TILE_M + wn * 32 + nt * 8 + tig * 2;
                    if (pos) {
                        if (col == row + BHALF) {
                            float pv = v0 * INV_T; g_pos[row] = pv; g_pos[col] = pv;
                        }
                        if (col + 1 == row + BHALF) {
                            float pv = v1 * INV_T; g_pos[row] = pv; g_pos[col + 1] = pv;
                        }
                    }
                    if (diag) {
                        if (col == row)     e0 = 0.0f;
                        if (col + 1 == row) e1 = 0.0f;
                    }
                }
                rsum[mt][h] += e0 + e1;
                csum[nt][0] += e0;
                csum[nt][1] += e1;
            }
    if (!diag) flush_csum(csum, jP, wn, g, tig);
}

// ---------------------------------------------------------------------------
// fused persistent kernel: normalize -> grid barrier -> symmetric GEMM with
// interleaved softmax-sum epilogue -> last-block loss tail.
// ---------------------------------------------------------------------------
__global__ void __launch_bounds__(NTHREADS) ntxent_fused_kernel(
    const float* __restrict__ z_i, const float* __restrict__ z_j,
    float* __restrict__ out)
{
    extern __shared__ __half smem[];
    __half* As  = smem;
    __half* Bs0 = smem + TILE_M * SM_STRIDE;
    __half* Bs1 = Bs0 + TILE_M * SM_STRIDE;

    const int tid  = threadIdx.x;
    const int warp = tid >> 5, lane = tid & 31;
    const int g    = lane >> 2, tig = lane & 3;
    const int wm   = warp >> 2, wn = warp & 3;   // 4x4 grid -> 32x32 per warp
    const unsigned nblk = gridDim.x;

    // ---- phase 1: normalize ----
    {
        int stride = nblk * 16;
        for (int r0 = blockIdx.x * 16 + warp; r0 < NROW; r0 += 2 * stride) {
            int r1 = r0 + stride;
            norm_row(r0, z_i, z_j, lane);
            if (r1 < NROW) norm_row(r1, z_i, z_j, lane);
        }
    }

    grid_barrier(nblk);

    // ---- phase 2: GEMM over balanced contiguous triangle ranges ----
    int bid = blockIdx.x;
    int q0  = (int)(((long long)bid * NPAIR) / nblk);
    int q1  = (int)(((long long)(bid + 1) * NPAIR) / nblk);

    if (q0 < q1) {
        int iCur, jCur;
        decode_tile(q0, iCur, jCur);

        load_tile_sync(As, g_zn + (size_t)iCur * TILE_M * DIM, tid);
        int iLoaded = iCur;
        load_tile_cp(Bs0, g_zn + (size_t)jCur * TILE_M * DIM, tid);
        cp_commit();

        const uint32_t sAs = (uint32_t)__cvta_generic_to_shared(As);
        const uint32_t sB0 = (uint32_t)__cvta_generic_to_shared(Bs0);
        const uint32_t sB1 = (uint32_t)__cvta_generic_to_shared(Bs1);
        const uint32_t STEP16 = 16u * SM_STRIDE * 2u;          // 16 rows
        const uint32_t aOff = ((wm * 32 + (lane & 15)) * SM_STRIDE + (lane >> 4) * 8) * 2;
        const uint32_t bOff = ((wn * 32 + (lane & 15)) * SM_STRIDE + (lane >> 4) * 8) * 2;

        unsigned accA[2][4][2], accB[2][4][2];
        float rsum[2][2];
        rsum[0][0] = rsum[0][1] = rsum[1][0] = rsum[1][1] = 0.f;

        int iP = -1, jP = -1;
        bool phaseA = true;

        for (int q = q0; q < q1; q++) {
            int buf = (q - q0) & 1;
            int iN = iCur, jN = jCur + 1;
            if (jN == NTILE) { iN++; jN = iN; }

            __syncthreads();                    // prior tile fully consumed

            if (q + 1 < q1)
                load_tile_cp(buf ? Bs0 : Bs1, g_zn + (size_t)jN * TILE_M * DIM, tid);
            cp_commit();                        // uniform group count

            if (iCur != iLoaded) {
                load_tile_sync(As, g_zn + (size_t)iCur * TILE_M * DIM, tid);
                iLoaded = iCur;
            }

            cp_wait1();
            __syncthreads();

            const uint32_t aA0 = sAs + aOff;
            const uint32_t aA1 = aA0 + STEP16;
            const uint32_t bB  = (buf ? sB1 : sB0) + bOff;
            const uint32_t bB1a = bB + STEP16;

            if (phaseA)
                mma_tile_f16(aA0, aA1, bB, bB1a, accA, accB,
                             iP >= 0, iP, jP, rsum, wm, wn, g, tig);
            else
                mma_tile_f16(aA0, aA1, bB, bB1a, accB, accA,
                             iP >= 0, iP, jP, rsum, wm, wn, g, tig);
            phaseA = !phaseA;

            if (iP >= 0 && iP != iCur)          // row iP's epilogue now complete
                flush_rsum(rsum, iP, wm, g, tig);

            iP = iCur; jP = jCur;
            iCur = iN; jCur = jN;
        }

        if (phaseA) epi_tile_f16(accB, iP, jP, rsum, wm, wn, g, tig);
        else        epi_tile_f16(accA, iP, jP, rsum, wm, wn, g, tig);
        flush_rsum(rsum, iP, wm, g, tig);
        cp_wait0();
    }

    // ---- phase 3: last block computes the loss ----
    __threadfence();
    __syncthreads();
    __shared__ unsigned amLast;
    if (tid == 0)
        amLast = (atomicAdd(&g_done, 1) == nblk - 1) ? 1u : 0u;
    __syncthreads();

    if (amLast) {
        __threadfence();
        float s = 0.0f;
        for (int k = tid; k < NROW; k += NTHREADS)
            s += logf(__ldcg(&g_sumexp[k])) - __ldcg(&g_pos[k]);
        #pragma unroll
        for (int o = 16; o; o >>= 1) s += __shfl_xor_sync(0xffffffffu, s, o);
        __shared__ float sw[16];
        if (lane == 0) sw[warp] = s;
        __syncthreads();
        if (tid == 0) {
            float v = 0.0f;
            #pragma unroll
            for (int w = 0; w < 16; w++) v += sw[w];
            out[0] = v / (float)NROW;
            g_done = 0;              // reset for next graph replay
        }
    }
}

extern "C" void kernel_launch(void* const* d_in, const int* in_sizes, int n_in,
                              void* d_out, int out_size) {
    const float* z_i = (const float*)d_in[0];
    const float* z_j = (const float*)d_in[1];
    float* out = (float*)d_out;

    int dev = 0, nsm = 148;
    cudaGetDevice(&dev);
    cudaDeviceGetAttribute(&nsm, cudaDevAttrMultiProcessorCount, dev);
    if (nsm < 1) nsm = 148;
    if (nsm > 512) nsm = 512;

    cudaFuncSetAttribute(ntxent_fused_kernel,
                         cudaFuncAttributeMaxDynamicSharedMemorySize, SMEM_BYTES);

    ntxent_fused_kernel<<<nsm, NTHREADS, SMEM_BYTES>>>(z_i, z_j, out);
}